// round 5
// baseline (speedup 1.0000x reference)
#include <cuda_runtime.h>
#include <cstdint>
#include <math.h>

#define BATCH 16
#define CH    512
#define NSP   1024
#define HEADS 4
#define HD    128
#define GROUPS_N 32
#define GSIZE (16*1024)
#define EPSV  1e-5f
#define ATT_SCALE 0.08838834764831845f

// ---------------------------------------------------------------------------
// Scratch (device globals). All GEMM operands stored pre-rounded to tf32.
// ---------------------------------------------------------------------------
__device__ float g_ht  [(size_t)BATCH*NSP*CH];
__device__ float g_qkvt[(size_t)BATCH*NSP*(3*CH)];
__device__ float g_vt  [(size_t)BATCH*HEADS*HD*NSP];
__device__ float g_s   [(size_t)BATCH*HEADS*NSP*NSP];
__device__ float g_ot  [(size_t)BATCH*NSP*CH];
__device__ float g_wq  [(size_t)(3*CH)*CH];
__device__ float g_wp  [(size_t)CH*CH];

// ---------------------------------------------------------------------------
// Helpers
// ---------------------------------------------------------------------------
__device__ __forceinline__ uint32_t smem_u32(const void* p){
    uint32_t a;
    asm("{ .reg .u64 t; cvta.to.shared.u64 t, %1; cvt.u32.u64 %0, t; }" : "=r"(a) : "l"(p));
    return a;
}
__device__ __forceinline__ uint32_t cvt_tf32(float f){
    uint32_t o; asm("cvt.rna.tf32.f32 %0, %1;" : "=r"(o) : "f"(f)); return o;
}
__device__ __forceinline__ float rnd_tf32(float f){ return __uint_as_float(cvt_tf32(f)); }

__device__ __forceinline__ void cp16(uint32_t dst, const float* src){
    asm volatile("cp.async.cg.shared.global [%0], [%1], 16;" :: "r"(dst), "l"(src) : "memory");
}
#define CP_COMMIT() asm volatile("cp.async.commit_group;" ::: "memory")
#define CP_WAIT1()  asm volatile("cp.async.wait_group 1;" ::: "memory")
#define CP_WAIT0()  asm volatile("cp.async.wait_group 0;" ::: "memory")

#define MMA8(c, a, b) \
    asm volatile("mma.sync.aligned.m16n8k8.row.col.f32.tf32.tf32.f32 " \
        "{%0,%1,%2,%3},{%4,%5,%6,%7},{%8,%9},{%0,%1,%2,%3};" \
        : "+f"((c)[0]), "+f"((c)[1]), "+f"((c)[2]), "+f"((c)[3]) \
        : "r"((a)[0]), "r"((a)[1]), "r"((a)[2]), "r"((a)[3]), \
          "r"((b)[0]), "r"((b)[1]))

// ---------------------------------------------------------------------------
// Weight pre-round
// ---------------------------------------------------------------------------
__global__ __launch_bounds__(256) void cvtw_kernel(
    const float* __restrict__ qw, const float* __restrict__ pw)
{
    int i = blockIdx.x * 256 + threadIdx.x;
    if (i < 3*CH*CH) g_wq[i] = rnd_tf32(qw[i]);
    if (i < CH*CH)   g_wp[i] = rnd_tf32(pw[i]);
}

// ---------------------------------------------------------------------------
// GroupNorm + transpose -> g_ht[b][n][c], tf32-rounded
// ---------------------------------------------------------------------------
__global__ __launch_bounds__(256) void gn_kernel(
    const float* __restrict__ x,
    const float* __restrict__ nw,
    const float* __restrict__ nb)
{
    __shared__ float t[16][257];
    int bg = blockIdx.x;
    int b = bg >> 5, g = bg & 31;
    const float* xp = x + (size_t)bg * GSIZE;
    int tid = threadIdx.x;

    float s = 0.f, s2 = 0.f;
    for (int i = tid; i < GSIZE; i += 256) { float v = xp[i]; s += v; s2 += v * v; }
    float* rs  = &t[0][0];
    float* rs2 = rs + 1024;
    rs[tid] = s; rs2[tid] = s2;
    __syncthreads();
    for (int o = 128; o > 0; o >>= 1) {
        if (tid < o) { rs[tid] += rs[tid + o]; rs2[tid] += rs2[tid + o]; }
        __syncthreads();
    }
    float mu   = rs[0] * (1.f / GSIZE);
    float var  = rs2[0] * (1.f / GSIZE) - mu * mu;
    float rinv = rsqrtf(var + EPSV);
    __syncthreads();

    int cl = tid & 15;
    float wc = nw[g * 16 + cl] * rinv;
    float bc = nb[g * 16 + cl] - mu * wc;
    float* hp = g_ht + (size_t)b * NSP * CH + g * 16;

    for (int n0 = 0; n0 < NSP; n0 += 256) {
#pragma unroll
        for (int c = 0; c < 16; c++) t[c][tid] = xp[c * NSP + n0 + tid];
        __syncthreads();
#pragma unroll
        for (int j = 0; j < 16; j++) {
            int nn = (tid >> 4) + j * 16;
            hp[(size_t)(n0 + nn) * CH + cl] = rnd_tf32(t[cl][nn] * wc + bc);
        }
        __syncthreads();
    }
}

// ---------------------------------------------------------------------------
// Softmax in-place over g_s rows; output probs tf32-rounded.
// ---------------------------------------------------------------------------
__global__ __launch_bounds__(256) void softmax_kernel()
{
    size_t row = (size_t)blockIdx.x * 8 + (threadIdx.x >> 5);
    int l = threadIdx.x & 31;
    float4* sp = (float4*)(g_s + row * NSP);

    float4 v[8];
    float m = -1e30f;
#pragma unroll
    for (int t = 0; t < 8; t++) {
        v[t] = sp[t * 32 + l];
        v[t].x *= ATT_SCALE; v[t].y *= ATT_SCALE; v[t].z *= ATT_SCALE; v[t].w *= ATT_SCALE;
        m = fmaxf(m, fmaxf(fmaxf(v[t].x, v[t].y), fmaxf(v[t].z, v[t].w)));
    }
#pragma unroll
    for (int o = 16; o > 0; o >>= 1) m = fmaxf(m, __shfl_xor_sync(0xffffffffu, m, o));
    float s = 0.f;
#pragma unroll
    for (int t = 0; t < 8; t++) {
        v[t].x = __expf(v[t].x - m); v[t].y = __expf(v[t].y - m);
        v[t].z = __expf(v[t].z - m); v[t].w = __expf(v[t].w - m);
        s += v[t].x + v[t].y + v[t].z + v[t].w;
    }
#pragma unroll
    for (int o = 16; o > 0; o >>= 1) s += __shfl_xor_sync(0xffffffffu, s, o);
    float inv = 1.f / s;
#pragma unroll
    for (int t = 0; t < 8; t++) {
        v[t].x = rnd_tf32(v[t].x * inv); v[t].y = rnd_tf32(v[t].y * inv);
        v[t].z = rnd_tf32(v[t].z * inv); v[t].w = rnd_tf32(v[t].w * inv);
        sp[t * 32 + l] = v[t];
    }
}

// ---------------------------------------------------------------------------
// tf32 mma.sync GEMM: D[128m x BNn] = A[m][K] * B[n][K]^T (both K-major)
// 256 threads = 8 warps. Modes 0/1/3: BN=256, warp grid 2x4, warp tile 64x64.
// Mode 2: BN=128, warp grid 4x2, warp tile 32x64.
// 2-stage cp.async pipeline, K-chunk 32, smem stride 36.
// Register double-buffered fragments. Epilogue in 128-col passes via smem.
// ---------------------------------------------------------------------------
#define BK 32
#define ASTR 36
#define SMEM_BIG   110592   // 2 stages * (128+256)*36*4
#define SMEM_SMALL 73728    // 2 stages * (128+128)*36*4

template<int MODE>
__global__ __launch_bounds__(256) void gemm_tc(
    const float* __restrict__ Wq, const float* __restrict__ Wp,
    const float* __restrict__ bias,
    const float* __restrict__ resid, float* __restrict__ outp)
{
    constexpr int BN     = (MODE == 2) ? 128 : 256;
    constexpr int WM     = (MODE == 2) ? 4 : 2;      // warps along m
    constexpr int MT     = 128 / (WM * 16);          // m16 tiles per warp (2 or 4)
    constexpr int TILE_A = 128 * ASTR;
    constexpr int TILE_B = BN * ASTR;
    constexpr int STAGE  = TILE_A + TILE_B;
    constexpr int NLD    = (128 + BN) * 8 / 256;     // float4 loads per thread per chunk
    constexpr int NP     = BN / 128;                 // epilogue passes

    extern __shared__ float sm[];
    const int tid = threadIdx.x;
    uint32_t smb = smem_u32(sm);

    int m0 = blockIdx.x * 128;
    int n0 = blockIdx.y * BN;
    int z  = blockIdx.z;

    const float *A, *B;
    int lda, ldb, K;
    if (MODE == 0) {
        A = g_ht + ((size_t)z * NSP + m0) * CH; lda = CH;
        B = Wq + (size_t)n0 * CH;               ldb = CH;  K = CH;
    } else if (MODE == 1) {
        int b = z >> 2, h = z & 3;
        const float* base = g_qkvt + (size_t)b * NSP * 1536;
        A = base + (size_t)m0 * 1536 + h * HD;
        B = base + (size_t)n0 * 1536 + 512 + h * HD;
        lda = 1536; ldb = 1536; K = HD;
    } else if (MODE == 2) {
        A = g_s  + (size_t)z * NSP * NSP + (size_t)m0 * NSP; lda = NSP; K = NSP;
        B = g_vt + (size_t)z * HD * NSP;                     ldb = NSP;
    } else {
        A = g_ot + ((size_t)z * NSP + m0) * CH; lda = CH;
        B = Wp + (size_t)n0 * CH;               ldb = CH;  K = CH;
    }

    const int lane = tid & 31, wid = tid >> 5;
    const int wm = wid % WM, wn = wid / WM;
    const int rA = lane >> 2, kA = lane & 3;

    float acc[MT][8][4];
#pragma unroll
    for (int i = 0; i < MT; i++)
#pragma unroll
        for (int j = 0; j < 8; j++)
#pragma unroll
            for (int q = 0; q < 4; q++) acc[i][j][q] = 0.f;

    const int nch = K / BK;

    // loader: thread tid copies NLD float4s; rows 0..127 = A, 128.. = B
    auto issue = [&](int ci) {
        int s = ci & 1;
        uint32_t st = smb + (uint32_t)(s * STAGE) * 4u;
        int k0 = ci * BK;
        int rr = tid >> 3, f = tid & 7;
#pragma unroll
        for (int t = 0; t < NLD; t++) {
            int row = t * 32 + rr;
            if (row < 128) {
                cp16(st + (uint32_t)(row * ASTR + f * 4) * 4u,
                     A + (size_t)row * lda + k0 + f * 4);
            } else {
                int r2 = row - 128;
                cp16(st + (uint32_t)(TILE_A + r2 * ASTR + f * 4) * 4u,
                     B + (size_t)r2 * ldb + k0 + f * 4);
            }
        }
    };

    issue(0); CP_COMMIT();

    for (int ci = 0; ci < nch; ci++) {
        if (ci + 1 < nch) { issue(ci + 1); CP_COMMIT(); CP_WAIT1(); }
        else              { CP_WAIT0(); }
        __syncthreads();

        const float* As = sm + (ci & 1) * STAGE;
        const float* Bs = As + TILE_A;

        uint32_t a[2][MT][4], b[2][8][2];

        {
            int kk = kA;
#pragma unroll
            for (int mt = 0; mt < MT; mt++) {
                int r = wm * (MT * 16) + mt * 16 + rA;
                a[0][mt][0] = __float_as_uint(As[r * ASTR + kk]);
                a[0][mt][1] = __float_as_uint(As[(r + 8) * ASTR + kk]);
                a[0][mt][2] = __float_as_uint(As[r * ASTR + kk + 4]);
                a[0][mt][3] = __float_as_uint(As[(r + 8) * ASTR + kk + 4]);
            }
#pragma unroll
            for (int nt = 0; nt < 8; nt++) {
                int n = wn * 64 + nt * 8 + rA;
                b[0][nt][0] = __float_as_uint(Bs[n * ASTR + kk]);
                b[0][nt][1] = __float_as_uint(Bs[n * ASTR + kk + 4]);
            }
        }

#pragma unroll
        for (int ks = 0; ks < 4; ks++) {
            int cur = ks & 1, nxt = cur ^ 1;
            if (ks < 3) {
                int kk = (ks + 1) * 8 + kA;
#pragma unroll
                for (int mt = 0; mt < MT; mt++) {
                    int r = wm * (MT * 16) + mt * 16 + rA;
                    a[nxt][mt][0] = __float_as_uint(As[r * ASTR + kk]);
                    a[nxt][mt][1] = __float_as_uint(As[(r + 8) * ASTR + kk]);
                    a[nxt][mt][2] = __float_as_uint(As[r * ASTR + kk + 4]);
                    a[nxt][mt][3] = __float_as_uint(As[(r + 8) * ASTR + kk + 4]);
                }
#pragma unroll
                for (int nt = 0; nt < 8; nt++) {
                    int n = wn * 64 + nt * 8 + rA;
                    b[nxt][nt][0] = __float_as_uint(Bs[n * ASTR + kk]);
                    b[nxt][nt][1] = __float_as_uint(Bs[n * ASTR + kk + 4]);
                }
            }
#pragma unroll
            for (int mt = 0; mt < MT; mt++)
#pragma unroll
                for (int nt = 0; nt < 8; nt++)
                    MMA8(acc[mt][nt], a[cur][mt], b[cur][nt]);
        }
        __syncthreads();
    }

    // ---------------- epilogue: NP passes of 128 cols ----------------
    float* Ds = sm;   // Ds[c][r], stride 133, 128x133 floats per pass
    for (int p = 0; p < NP; p++) {
        if ((wn >> 1) == p || NP == 1) {
#pragma unroll
            for (int mt = 0; mt < MT; mt++)
#pragma unroll
                for (int nt = 0; nt < 8; nt++) {
                    int r = wm * (MT * 16) + mt * 16 + rA;
                    int c = (NP == 1 ? wn : (wn & 1)) * 64 + nt * 8 + kA * 2;
                    Ds[c * 133 + r]           = acc[mt][nt][0];
                    Ds[(c + 1) * 133 + r]     = acc[mt][nt][1];
                    Ds[c * 133 + r + 8]       = acc[mt][nt][2];
                    Ds[(c + 1) * 133 + r + 8] = acc[mt][nt][3];
                }
        }
        __syncthreads();

        int cbase = n0 + p * 128;
        if (MODE == 1) {
#pragma unroll 8
            for (int it = 0; it < 64; it++) {
                int e = it * 256 + tid; int r = e >> 7; int c = e & 127;
                g_s[(size_t)z * NSP * NSP + (size_t)(m0 + r) * NSP + cbase + c] = Ds[c * 133 + r];
            }
        } else if (MODE == 2) {
#pragma unroll 8
            for (int it = 0; it < 64; it++) {
                int e = it * 256 + tid; int r = e >> 7; int c = e & 127;
                g_ot[((size_t)(z >> 2) * NSP + m0 + r) * CH + (z & 3) * HD + c] = rnd_tf32(Ds[c * 133 + r]);
            }
        } else if (MODE == 0) {
            if (cbase < 1024) {   // Q/K -> g_qkvt[b][n][o]
#pragma unroll 8
                for (int it = 0; it < 64; it++) {
                    int e = it * 256 + tid; int r = e >> 7; int c = e & 127;
                    g_qkvt[((size_t)z * NSP + m0 + r) * 1536 + cbase + c] =
                        rnd_tf32(Ds[c * 133 + r] + bias[cbase + c]);
                }
            } else {              // V transposed -> g_vt[b,h][d][m]
                int h = (cbase - 1024) >> 7;
#pragma unroll 8
                for (int it = 0; it < 64; it++) {
                    int e = it * 256 + tid; int c = e >> 7; int r = e & 127;
                    g_vt[(((size_t)z * HEADS + h) * HD + c) * NSP + m0 + r] =
                        rnd_tf32(Ds[c * 133 + r] + bias[cbase + c]);
                }
            }
        } else {                  // MODE 3: bias + residual, transposed -> out
#pragma unroll 8
            for (int it = 0; it < 64; it++) {
                int e = it * 256 + tid; int c = e >> 7; int r = e & 127;
                size_t off = ((size_t)z * CH + cbase + c) * NSP + m0 + r;
                outp[off] = Ds[c * 133 + r] + bias[cbase + c] + resid[off];
            }
        }
        __syncthreads();
    }
}

// ---------------------------------------------------------------------------
// Launch
// ---------------------------------------------------------------------------
extern "C" void kernel_launch(void* const* d_in, const int* in_sizes, int n_in,
                              void* d_out, int out_size)
{
    const float* x      = (const float*)d_in[0];
    const float* norm_w = (const float*)d_in[1];
    const float* norm_b = (const float*)d_in[2];
    const float* qkv_w  = (const float*)d_in[3];
    const float* qkv_b  = (const float*)d_in[4];
    const float* proj_w = (const float*)d_in[5];
    const float* proj_b = (const float*)d_in[6];
    float* out = (float*)d_out;

    float* wq; cudaGetSymbolAddress((void**)&wq, g_wq);
    float* wp; cudaGetSymbolAddress((void**)&wp, g_wp);

    cudaFuncSetAttribute(gemm_tc<0>, cudaFuncAttributeMaxDynamicSharedMemorySize, SMEM_BIG);
    cudaFuncSetAttribute(gemm_tc<1>, cudaFuncAttributeMaxDynamicSharedMemorySize, SMEM_BIG);
    cudaFuncSetAttribute(gemm_tc<2>, cudaFuncAttributeMaxDynamicSharedMemorySize, SMEM_SMALL);
    cudaFuncSetAttribute(gemm_tc<3>, cudaFuncAttributeMaxDynamicSharedMemorySize, SMEM_BIG);

    cvtw_kernel<<<(3 * CH * CH + 255) / 256, 256>>>(qkv_w, proj_w);
    gn_kernel<<<BATCH * GROUPS_N, 256>>>(x, norm_w, norm_b);

    gemm_tc<0><<<dim3(NSP / 128, 1536 / 256, BATCH), 256, SMEM_BIG>>>(wq, nullptr, qkv_b, nullptr, nullptr);
    gemm_tc<1><<<dim3(NSP / 128, NSP / 256, BATCH * HEADS), 256, SMEM_BIG>>>(nullptr, nullptr, nullptr, nullptr, nullptr);
    softmax_kernel<<<(BATCH * HEADS * NSP) / 8, 256>>>();
    gemm_tc<2><<<dim3(NSP / 128, 1, BATCH * HEADS), 256, SMEM_SMALL>>>(nullptr, nullptr, nullptr, nullptr, nullptr);
    gemm_tc<3><<<dim3(NSP / 128, CH / 256, BATCH), 256, SMEM_BIG>>>(nullptr, wp, proj_b, x, out);
}

// round 6
// speedup vs baseline: 1.1531x; 1.1531x over previous
#include <cuda_runtime.h>
#include <cstdint>
#include <math.h>

#define BATCH 16
#define CH    512
#define NSP   1024
#define HEADS 4
#define HD    128
#define GROUPS_N 32
#define GSIZE (16*1024)
#define EPSV  1e-5f
#define ATT_SCALE 0.08838834764831845f

// ---------------------------------------------------------------------------
// Scratch (device globals). All GEMM operands stored pre-rounded to tf32.
// ---------------------------------------------------------------------------
__device__ float g_ht  [(size_t)BATCH*NSP*CH];
__device__ float g_qkvt[(size_t)BATCH*NSP*(3*CH)];
__device__ float g_vt  [(size_t)BATCH*HEADS*HD*NSP];
__device__ float g_s   [(size_t)BATCH*HEADS*NSP*NSP];
__device__ float g_ot  [(size_t)BATCH*NSP*CH];
__device__ float g_wq  [(size_t)(3*CH)*CH];
__device__ float g_wp  [(size_t)CH*CH];

// ---------------------------------------------------------------------------
// Helpers
// ---------------------------------------------------------------------------
__device__ __forceinline__ uint32_t smem_u32(const void* p){
    uint32_t a;
    asm("{ .reg .u64 t; cvta.to.shared.u64 t, %1; cvt.u32.u64 %0, t; }" : "=r"(a) : "l"(p));
    return a;
}
__device__ __forceinline__ uint32_t cvt_tf32(float f){
    uint32_t o; asm("cvt.rna.tf32.f32 %0, %1;" : "=r"(o) : "f"(f)); return o;
}
__device__ __forceinline__ float rnd_tf32(float f){ return __uint_as_float(cvt_tf32(f)); }

__device__ __forceinline__ void cp16(uint32_t dst, const float* src){
    asm volatile("cp.async.cg.shared.global [%0], [%1], 16;" :: "r"(dst), "l"(src) : "memory");
}
#define CP_COMMIT() asm volatile("cp.async.commit_group;" ::: "memory")
#define CP_WAIT1()  asm volatile("cp.async.wait_group 1;" ::: "memory")
#define CP_WAIT0()  asm volatile("cp.async.wait_group 0;" ::: "memory")

#define MMA8(c, a, b) \
    asm volatile("mma.sync.aligned.m16n8k8.row.col.f32.tf32.tf32.f32 " \
        "{%0,%1,%2,%3},{%4,%5,%6,%7},{%8,%9},{%0,%1,%2,%3};" \
        : "+f"((c)[0]), "+f"((c)[1]), "+f"((c)[2]), "+f"((c)[3]) \
        : "r"((a)[0]), "r"((a)[1]), "r"((a)[2]), "r"((a)[3]), \
          "r"((b)[0]), "r"((b)[1]))

// ---------------------------------------------------------------------------
// Weight pre-round
// ---------------------------------------------------------------------------
__global__ __launch_bounds__(256) void cvtw_kernel(
    const float* __restrict__ qw, const float* __restrict__ pw)
{
    int i = blockIdx.x * 256 + threadIdx.x;
    if (i < 3*CH*CH) g_wq[i] = rnd_tf32(qw[i]);
    if (i < CH*CH)   g_wp[i] = rnd_tf32(pw[i]);
}

// ---------------------------------------------------------------------------
// GroupNorm + transpose -> g_ht[b][n][c], tf32-rounded
// ---------------------------------------------------------------------------
__global__ __launch_bounds__(256) void gn_kernel(
    const float* __restrict__ x,
    const float* __restrict__ nw,
    const float* __restrict__ nb)
{
    __shared__ float t[16][257];
    int bg = blockIdx.x;
    int b = bg >> 5, g = bg & 31;
    const float* xp = x + (size_t)bg * GSIZE;
    int tid = threadIdx.x;

    float s = 0.f, s2 = 0.f;
    for (int i = tid; i < GSIZE; i += 256) { float v = xp[i]; s += v; s2 += v * v; }
    float* rs  = &t[0][0];
    float* rs2 = rs + 1024;
    rs[tid] = s; rs2[tid] = s2;
    __syncthreads();
    for (int o = 128; o > 0; o >>= 1) {
        if (tid < o) { rs[tid] += rs[tid + o]; rs2[tid] += rs2[tid + o]; }
        __syncthreads();
    }
    float mu   = rs[0] * (1.f / GSIZE);
    float var  = rs2[0] * (1.f / GSIZE) - mu * mu;
    float rinv = rsqrtf(var + EPSV);
    __syncthreads();

    int cl = tid & 15;
    float wc = nw[g * 16 + cl] * rinv;
    float bc = nb[g * 16 + cl] - mu * wc;
    float* hp = g_ht + (size_t)b * NSP * CH + g * 16;

    for (int n0 = 0; n0 < NSP; n0 += 256) {
#pragma unroll
        for (int c = 0; c < 16; c++) t[c][tid] = xp[c * NSP + n0 + tid];
        __syncthreads();
#pragma unroll
        for (int j = 0; j < 16; j++) {
            int nn = (tid >> 4) + j * 16;
            hp[(size_t)(n0 + nn) * CH + cl] = rnd_tf32(t[cl][nn] * wc + bc);
        }
        __syncthreads();
    }
}

// ---------------------------------------------------------------------------
// Softmax in-place over g_s rows; output probs tf32-rounded.
// ---------------------------------------------------------------------------
__global__ __launch_bounds__(256) void softmax_kernel()
{
    size_t row = (size_t)blockIdx.x * 8 + (threadIdx.x >> 5);
    int l = threadIdx.x & 31;
    float4* sp = (float4*)(g_s + row * NSP);

    float4 v[8];
    float m = -1e30f;
#pragma unroll
    for (int t = 0; t < 8; t++) {
        v[t] = sp[t * 32 + l];
        v[t].x *= ATT_SCALE; v[t].y *= ATT_SCALE; v[t].z *= ATT_SCALE; v[t].w *= ATT_SCALE;
        m = fmaxf(m, fmaxf(fmaxf(v[t].x, v[t].y), fmaxf(v[t].z, v[t].w)));
    }
#pragma unroll
    for (int o = 16; o > 0; o >>= 1) m = fmaxf(m, __shfl_xor_sync(0xffffffffu, m, o));
    float s = 0.f;
#pragma unroll
    for (int t = 0; t < 8; t++) {
        v[t].x = __expf(v[t].x - m); v[t].y = __expf(v[t].y - m);
        v[t].z = __expf(v[t].z - m); v[t].w = __expf(v[t].w - m);
        s += v[t].x + v[t].y + v[t].z + v[t].w;
    }
#pragma unroll
    for (int o = 16; o > 0; o >>= 1) s += __shfl_xor_sync(0xffffffffu, s, o);
    float inv = 1.f / s;
#pragma unroll
    for (int t = 0; t < 8; t++) {
        v[t].x = rnd_tf32(v[t].x * inv); v[t].y = rnd_tf32(v[t].y * inv);
        v[t].z = rnd_tf32(v[t].z * inv); v[t].w = rnd_tf32(v[t].w * inv);
        sp[t * 32 + l] = v[t];
    }
}

// ---------------------------------------------------------------------------
// tf32 mma.sync GEMM: D[128m x 128n] = A[m][K] * B[n][K]^T (both K-major)
// 128 threads = 4 warps (2 x 2); warp tile 64x64; register double-buffered
// fragments; 2-stage cp.async pipeline (73.7 KB smem -> 3 CTAs/SM).
// ---------------------------------------------------------------------------
#define BK 32
#define ASTR 36
#define TILE_F (128*ASTR)
#define STAGE_F (2*TILE_F)
#define GEMM_SMEM (2*STAGE_F*4)   // 73728 bytes

template<int MODE>
__global__ __launch_bounds__(128, 3) void gemm_tc(
    const float* __restrict__ Wq, const float* __restrict__ Wp,
    const float* __restrict__ bias,
    const float* __restrict__ resid, float* __restrict__ outp)
{
    extern __shared__ float sm[];
    const int tid = threadIdx.x;
    uint32_t smb = smem_u32(sm);

    int m0 = blockIdx.x * 128;
    int n0 = blockIdx.y * 128;
    int z  = blockIdx.z;

    const float *A, *B;
    int lda, ldb, K;
    if (MODE == 0) {
        A = g_ht + ((size_t)z * NSP + m0) * CH; lda = CH;
        B = Wq + (size_t)n0 * CH;               ldb = CH;  K = CH;
    } else if (MODE == 1) {
        int b = z >> 2, h = z & 3;
        const float* base = g_qkvt + (size_t)b * NSP * 1536;
        A = base + (size_t)m0 * 1536 + h * HD;
        B = base + (size_t)n0 * 1536 + 512 + h * HD;
        lda = 1536; ldb = 1536; K = HD;
    } else if (MODE == 2) {
        A = g_s  + (size_t)z * NSP * NSP + (size_t)m0 * NSP; lda = NSP; K = NSP;
        B = g_vt + (size_t)z * HD * NSP;                     ldb = NSP;
    } else {
        A = g_ot + ((size_t)z * NSP + m0) * CH; lda = CH;
        B = Wp + (size_t)n0 * CH;               ldb = CH;  K = CH;
    }

    const int lane = tid & 31, wid = tid >> 5;
    const int wm = wid & 1, wn = wid >> 1;     // 2 x 2 warp grid, 64x64 tiles
    const int r_ = tid >> 3;                   // 0..15
    const int f_ = tid & 7;                    // 0..7

    float acc[4][8][4];
#pragma unroll
    for (int i = 0; i < 4; i++)
#pragma unroll
        for (int j = 0; j < 8; j++)
#pragma unroll
            for (int q = 0; q < 4; q++) acc[i][j][q] = 0.f;

    const int nch = K / BK;

    auto issue = [&](int ci) {
        int s = ci & 1;
        uint32_t as = smb + (uint32_t)(s * STAGE_F) * 4u;
        uint32_t bs = as + (uint32_t)TILE_F * 4u;
        int k0 = ci * BK;
#pragma unroll
        for (int t = 0; t < 8; t++) {
            int r = t * 16 + r_;
            cp16(as + (uint32_t)(r * ASTR + f_ * 4) * 4u, A + (size_t)r * lda + k0 + f_ * 4);
            cp16(bs + (uint32_t)(r * ASTR + f_ * 4) * 4u, B + (size_t)r * ldb + k0 + f_ * 4);
        }
    };

    issue(0); CP_COMMIT();

    const int rA = lane >> 2, kA = lane & 3;

    for (int ci = 0; ci < nch; ci++) {
        if (ci + 1 < nch) { issue(ci + 1); CP_COMMIT(); CP_WAIT1(); }
        else              { CP_WAIT0(); }
        __syncthreads();

        const float* As = sm + (ci & 1) * STAGE_F;
        const float* Bs = As + TILE_F;

        // fragment double-buffer across the 4 k8-steps
        uint32_t a[2][4][4], b[2][8][2];

        {
            int kk = kA;            // ks = 0
#pragma unroll
            for (int mt = 0; mt < 4; mt++) {
                int r = wm * 64 + mt * 16 + rA;
                a[0][mt][0] = __float_as_uint(As[r * ASTR + kk]);
                a[0][mt][1] = __float_as_uint(As[(r + 8) * ASTR + kk]);
                a[0][mt][2] = __float_as_uint(As[r * ASTR + kk + 4]);
                a[0][mt][3] = __float_as_uint(As[(r + 8) * ASTR + kk + 4]);
            }
#pragma unroll
            for (int nt = 0; nt < 8; nt++) {
                int n = wn * 64 + nt * 8 + rA;
                b[0][nt][0] = __float_as_uint(Bs[n * ASTR + kk]);
                b[0][nt][1] = __float_as_uint(Bs[n * ASTR + kk + 4]);
            }
        }

#pragma unroll
        for (int ks = 0; ks < 4; ks++) {
            int cur = ks & 1, nxt = cur ^ 1;
            if (ks < 3) {
                int kk = (ks + 1) * 8 + kA;
#pragma unroll
                for (int mt = 0; mt < 4; mt++) {
                    int r = wm * 64 + mt * 16 + rA;
                    a[nxt][mt][0] = __float_as_uint(As[r * ASTR + kk]);
                    a[nxt][mt][1] = __float_as_uint(As[(r + 8) * ASTR + kk]);
                    a[nxt][mt][2] = __float_as_uint(As[r * ASTR + kk + 4]);
                    a[nxt][mt][3] = __float_as_uint(As[(r + 8) * ASTR + kk + 4]);
                }
#pragma unroll
                for (int nt = 0; nt < 8; nt++) {
                    int n = wn * 64 + nt * 8 + rA;
                    b[nxt][nt][0] = __float_as_uint(Bs[n * ASTR + kk]);
                    b[nxt][nt][1] = __float_as_uint(Bs[n * ASTR + kk + 4]);
                }
            }
#pragma unroll
            for (int mt = 0; mt < 4; mt++)
#pragma unroll
                for (int nt = 0; nt < 8; nt++)
                    MMA8(acc[mt][nt], a[cur][mt], b[cur][nt]);
        }
        __syncthreads();
    }

    // Stage D through smem: Ds[col][row], stride 133
    float* Ds = sm;
#pragma unroll
    for (int mt = 0; mt < 4; mt++)
#pragma unroll
        for (int nt = 0; nt < 8; nt++) {
            int r = wm * 64 + mt * 16 + (lane >> 2);
            int c = wn * 64 + nt * 8 + (lane & 3) * 2;
            Ds[c * 133 + r]           = acc[mt][nt][0];
            Ds[(c + 1) * 133 + r]     = acc[mt][nt][1];
            Ds[c * 133 + r + 8]       = acc[mt][nt][2];
            Ds[(c + 1) * 133 + r + 8] = acc[mt][nt][3];
        }
    __syncthreads();

    if (MODE == 1) {
#pragma unroll 8
        for (int p = 0; p < 128; p++) {
            int e = p * 128 + tid; int r = e >> 7; int c = e & 127;
            g_s[(size_t)z * NSP * NSP + (size_t)(m0 + r) * NSP + n0 + c] = Ds[c * 133 + r];
        }
    } else if (MODE == 2) {
#pragma unroll 8
        for (int p = 0; p < 128; p++) {
            int e = p * 128 + tid; int r = e >> 7; int c = e & 127;
            g_ot[((size_t)(z >> 2) * NSP + m0 + r) * CH + (z & 3) * HD + c] = rnd_tf32(Ds[c * 133 + r]);
        }
    } else if (MODE == 0) {
        if (n0 < 1024) {
#pragma unroll 8
            for (int p = 0; p < 128; p++) {
                int e = p * 128 + tid; int r = e >> 7; int c = e & 127;
                g_qkvt[((size_t)z * NSP + m0 + r) * 1536 + n0 + c] = rnd_tf32(Ds[c * 133 + r] + bias[n0 + c]);
            }
        } else {
            int h = (n0 - 1024) >> 7;
#pragma unroll 8
            for (int p = 0; p < 128; p++) {
                int e = p * 128 + tid; int c = e >> 7; int r = e & 127;
                g_vt[(((size_t)z * HEADS + h) * HD + c) * NSP + m0 + r] = rnd_tf32(Ds[c * 133 + r] + bias[n0 + c]);
            }
        }
    } else {
#pragma unroll 8
        for (int p = 0; p < 128; p++) {
            int e = p * 128 + tid; int c = e >> 7; int r = e & 127;
            size_t off = ((size_t)z * CH + n0 + c) * NSP + m0 + r;
            outp[off] = Ds[c * 133 + r] + bias[n0 + c] + resid[off];
        }
    }
}

// ---------------------------------------------------------------------------
// Launch
// ---------------------------------------------------------------------------
extern "C" void kernel_launch(void* const* d_in, const int* in_sizes, int n_in,
                              void* d_out, int out_size)
{
    const float* x      = (const float*)d_in[0];
    const float* norm_w = (const float*)d_in[1];
    const float* norm_b = (const float*)d_in[2];
    const float* qkv_w  = (const float*)d_in[3];
    const float* qkv_b  = (const float*)d_in[4];
    const float* proj_w = (const float*)d_in[5];
    const float* proj_b = (const float*)d_in[6];
    float* out = (float*)d_out;

    float* wq; cudaGetSymbolAddress((void**)&wq, g_wq);
    float* wp; cudaGetSymbolAddress((void**)&wp, g_wp);

    cudaFuncSetAttribute(gemm_tc<0>, cudaFuncAttributeMaxDynamicSharedMemorySize, GEMM_SMEM);
    cudaFuncSetAttribute(gemm_tc<1>, cudaFuncAttributeMaxDynamicSharedMemorySize, GEMM_SMEM);
    cudaFuncSetAttribute(gemm_tc<2>, cudaFuncAttributeMaxDynamicSharedMemorySize, GEMM_SMEM);
    cudaFuncSetAttribute(gemm_tc<3>, cudaFuncAttributeMaxDynamicSharedMemorySize, GEMM_SMEM);

    cvtw_kernel<<<(3 * CH * CH + 255) / 256, 256>>>(qkv_w, proj_w);
    gn_kernel<<<BATCH * GROUPS_N, 256>>>(x, norm_w, norm_b);

    gemm_tc<0><<<dim3(NSP / 128, 1536 / 128, BATCH), 128, GEMM_SMEM>>>(wq, nullptr, qkv_b, nullptr, nullptr);
    gemm_tc<1><<<dim3(NSP / 128, NSP / 128, BATCH * HEADS), 128, GEMM_SMEM>>>(nullptr, nullptr, nullptr, nullptr, nullptr);
    softmax_kernel<<<(BATCH * HEADS * NSP) / 8, 256>>>();
    gemm_tc<2><<<dim3(NSP / 128, 1, BATCH * HEADS), 128, GEMM_SMEM>>>(nullptr, nullptr, nullptr, nullptr, nullptr);
    gemm_tc<3><<<dim3(NSP / 128, CH / 128, BATCH), 128, GEMM_SMEM>>>(nullptr, wp, proj_b, x, out);
}

// round 8
// speedup vs baseline: 1.3103x; 1.1363x over previous
#include <cuda_runtime.h>
#include <cstdint>
#include <math.h>

#define BATCH 16
#define CH    512
#define NSP   1024
#define HEADS 4
#define HD    128
#define GROUPS_N 32
#define GSIZE (16*1024)
#define EPSV  1e-5f
#define ATT_SCALE 0.08838834764831845f

// ---------------------------------------------------------------------------
// Scratch (device globals). All GEMM operands stored pre-rounded to tf32.
// ---------------------------------------------------------------------------
__device__ float g_ht  [(size_t)BATCH*NSP*CH];
__device__ float g_qkvt[(size_t)BATCH*NSP*(3*CH)];
__device__ float g_vt  [(size_t)BATCH*HEADS*HD*NSP];
__device__ float g_ot  [(size_t)BATCH*NSP*CH];
__device__ float g_wq  [(size_t)(3*CH)*CH];
__device__ float g_wp  [(size_t)CH*CH];

// ---------------------------------------------------------------------------
// Helpers
// ---------------------------------------------------------------------------
__device__ __forceinline__ uint32_t smem_u32(const void* p){
    uint32_t a;
    asm("{ .reg .u64 t; cvta.to.shared.u64 t, %1; cvt.u32.u64 %0, t; }" : "=r"(a) : "l"(p));
    return a;
}
__device__ __forceinline__ uint32_t cvt_tf32(float f){
    uint32_t o; asm("cvt.rna.tf32.f32 %0, %1;" : "=r"(o) : "f"(f)); return o;
}
__device__ __forceinline__ float rnd_tf32(float f){ return __uint_as_float(cvt_tf32(f)); }

__device__ __forceinline__ void cp16(uint32_t dst, const float* src){
    asm volatile("cp.async.cg.shared.global [%0], [%1], 16;" :: "r"(dst), "l"(src) : "memory");
}
#define CP_COMMIT() asm volatile("cp.async.commit_group;" ::: "memory")
#define CP_WAIT1()  asm volatile("cp.async.wait_group 1;" ::: "memory")
#define CP_WAIT0()  asm volatile("cp.async.wait_group 0;" ::: "memory")

#define MMA8(c, a, b) \
    asm volatile("mma.sync.aligned.m16n8k8.row.col.f32.tf32.tf32.f32 " \
        "{%0,%1,%2,%3},{%4,%5,%6,%7},{%8,%9},{%0,%1,%2,%3};" \
        : "+f"((c)[0]), "+f"((c)[1]), "+f"((c)[2]), "+f"((c)[3]) \
        : "r"((a)[0]), "r"((a)[1]), "r"((a)[2]), "r"((a)[3]), \
          "r"((b)[0]), "r"((b)[1]))

// ---------------------------------------------------------------------------
// Weight pre-round
// ---------------------------------------------------------------------------
__global__ __launch_bounds__(256) void cvtw_kernel(
    const float* __restrict__ qw, const float* __restrict__ pw)
{
    int i = blockIdx.x * 256 + threadIdx.x;
    if (i < 3*CH*CH) g_wq[i] = rnd_tf32(qw[i]);
    if (i < CH*CH)   g_wp[i] = rnd_tf32(pw[i]);
}

// ---------------------------------------------------------------------------
// GroupNorm + transpose -> g_ht[b][n][c], tf32-rounded
// ---------------------------------------------------------------------------
__global__ __launch_bounds__(256) void gn_kernel(
    const float* __restrict__ x,
    const float* __restrict__ nw,
    const float* __restrict__ nb)
{
    __shared__ float t[16][257];
    int bg = blockIdx.x;
    int b = bg >> 5, g = bg & 31;
    const float* xp = x + (size_t)bg * GSIZE;
    int tid = threadIdx.x;

    float s = 0.f, s2 = 0.f;
    for (int i = tid; i < GSIZE; i += 256) { float v = xp[i]; s += v; s2 += v * v; }
    float* rs  = &t[0][0];
    float* rs2 = rs + 1024;
    rs[tid] = s; rs2[tid] = s2;
    __syncthreads();
    for (int o = 128; o > 0; o >>= 1) {
        if (tid < o) { rs[tid] += rs[tid + o]; rs2[tid] += rs2[tid + o]; }
        __syncthreads();
    }
    float mu   = rs[0] * (1.f / GSIZE);
    float var  = rs2[0] * (1.f / GSIZE) - mu * mu;
    float rinv = rsqrtf(var + EPSV);
    __syncthreads();

    int cl = tid & 15;
    float wc = nw[g * 16 + cl] * rinv;
    float bc = nb[g * 16 + cl] - mu * wc;
    float* hp = g_ht + (size_t)b * NSP * CH + g * 16;

    for (int n0 = 0; n0 < NSP; n0 += 256) {
#pragma unroll
        for (int c = 0; c < 16; c++) t[c][tid] = xp[c * NSP + n0 + tid];
        __syncthreads();
#pragma unroll
        for (int j = 0; j < 16; j++) {
            int nn = (tid >> 4) + j * 16;
            hp[(size_t)(n0 + nn) * CH + cl] = rnd_tf32(t[cl][nn] * wc + bc);
        }
        __syncthreads();
    }
}

// ---------------------------------------------------------------------------
// tf32 mma.sync GEMM (modes 0 and 3; attention is fused separately).
// 128 threads = 4 warps (2 x 2); warp tile 64x64; register double-buffered
// fragments; 2-stage cp.async pipeline (73.7 KB smem -> 3 CTAs/SM).
// ---------------------------------------------------------------------------
#define BK 32
#define ASTR 36
#define TILE_F (128*ASTR)
#define STAGE_F (2*TILE_F)
#define GEMM_SMEM (2*STAGE_F*4)   // 73728 bytes

template<int MODE>
__global__ __launch_bounds__(128, 3) void gemm_tc(
    const float* __restrict__ Wq, const float* __restrict__ Wp,
    const float* __restrict__ bias,
    const float* __restrict__ resid, float* __restrict__ outp)
{
    extern __shared__ float sm[];
    const int tid = threadIdx.x;
    uint32_t smb = smem_u32(sm);

    int m0 = blockIdx.x * 128;
    int n0 = blockIdx.y * 128;
    int z  = blockIdx.z;

    const float *A, *B;
    int lda, ldb, K;
    if (MODE == 0) {
        A = g_ht + ((size_t)z * NSP + m0) * CH; lda = CH;
        B = Wq + (size_t)n0 * CH;               ldb = CH;  K = CH;
    } else {
        A = g_ot + ((size_t)z * NSP + m0) * CH; lda = CH;
        B = Wp + (size_t)n0 * CH;               ldb = CH;  K = CH;
    }

    const int lane = tid & 31, wid = tid >> 5;
    const int wm = wid & 1, wn = wid >> 1;
    const int r_ = tid >> 3;
    const int f_ = tid & 7;

    float acc[4][8][4];
#pragma unroll
    for (int i = 0; i < 4; i++)
#pragma unroll
        for (int j = 0; j < 8; j++)
#pragma unroll
            for (int q = 0; q < 4; q++) acc[i][j][q] = 0.f;

    const int nch = K / BK;

    auto issue = [&](int ci) {
        int s = ci & 1;
        uint32_t as = smb + (uint32_t)(s * STAGE_F) * 4u;
        uint32_t bs = as + (uint32_t)TILE_F * 4u;
        int k0 = ci * BK;
#pragma unroll
        for (int t = 0; t < 8; t++) {
            int r = t * 16 + r_;
            cp16(as + (uint32_t)(r * ASTR + f_ * 4) * 4u, A + (size_t)r * lda + k0 + f_ * 4);
            cp16(bs + (uint32_t)(r * ASTR + f_ * 4) * 4u, B + (size_t)r * ldb + k0 + f_ * 4);
        }
    };

    issue(0); CP_COMMIT();

    const int rA = lane >> 2, kA = lane & 3;

    for (int ci = 0; ci < nch; ci++) {
        if (ci + 1 < nch) { issue(ci + 1); CP_COMMIT(); CP_WAIT1(); }
        else              { CP_WAIT0(); }
        __syncthreads();

        const float* As = sm + (ci & 1) * STAGE_F;
        const float* Bs = As + TILE_F;

        uint32_t a[2][4][4], b[2][8][2];
        {
            int kk = kA;
#pragma unroll
            for (int mt = 0; mt < 4; mt++) {
                int r = wm * 64 + mt * 16 + rA;
                a[0][mt][0] = __float_as_uint(As[r * ASTR + kk]);
                a[0][mt][1] = __float_as_uint(As[(r + 8) * ASTR + kk]);
                a[0][mt][2] = __float_as_uint(As[r * ASTR + kk + 4]);
                a[0][mt][3] = __float_as_uint(As[(r + 8) * ASTR + kk + 4]);
            }
#pragma unroll
            for (int nt = 0; nt < 8; nt++) {
                int n = wn * 64 + nt * 8 + rA;
                b[0][nt][0] = __float_as_uint(Bs[n * ASTR + kk]);
                b[0][nt][1] = __float_as_uint(Bs[n * ASTR + kk + 4]);
            }
        }

#pragma unroll
        for (int ks = 0; ks < 4; ks++) {
            int cur = ks & 1, nxt = cur ^ 1;
            if (ks < 3) {
                int kk = (ks + 1) * 8 + kA;
#pragma unroll
                for (int mt = 0; mt < 4; mt++) {
                    int r = wm * 64 + mt * 16 + rA;
                    a[nxt][mt][0] = __float_as_uint(As[r * ASTR + kk]);
                    a[nxt][mt][1] = __float_as_uint(As[(r + 8) * ASTR + kk]);
                    a[nxt][mt][2] = __float_as_uint(As[r * ASTR + kk + 4]);
                    a[nxt][mt][3] = __float_as_uint(As[(r + 8) * ASTR + kk + 4]);
                }
#pragma unroll
                for (int nt = 0; nt < 8; nt++) {
                    int n = wn * 64 + nt * 8 + rA;
                    b[nxt][nt][0] = __float_as_uint(Bs[n * ASTR + kk]);
                    b[nxt][nt][1] = __float_as_uint(Bs[n * ASTR + kk + 4]);
                }
            }
#pragma unroll
            for (int mt = 0; mt < 4; mt++)
#pragma unroll
                for (int nt = 0; nt < 8; nt++)
                    MMA8(acc[mt][nt], a[cur][mt], b[cur][nt]);
        }
        __syncthreads();
    }

    // Stage D through smem: Ds[col][row], stride 133
    float* Ds = sm;
#pragma unroll
    for (int mt = 0; mt < 4; mt++)
#pragma unroll
        for (int nt = 0; nt < 8; nt++) {
            int r = wm * 64 + mt * 16 + (lane >> 2);
            int c = wn * 64 + nt * 8 + (lane & 3) * 2;
            Ds[c * 133 + r]           = acc[mt][nt][0];
            Ds[(c + 1) * 133 + r]     = acc[mt][nt][1];
            Ds[c * 133 + r + 8]       = acc[mt][nt][2];
            Ds[(c + 1) * 133 + r + 8] = acc[mt][nt][3];
        }
    __syncthreads();

    if (MODE == 0) {
        if (n0 < 1024) {   // Q/K -> g_qkvt[b][n][o]
#pragma unroll 8
            for (int p = 0; p < 128; p++) {
                int e = p * 128 + tid; int r = e >> 7; int c = e & 127;
                g_qkvt[((size_t)z * NSP + m0 + r) * 1536 + n0 + c] = rnd_tf32(Ds[c * 133 + r] + bias[n0 + c]);
            }
        } else {           // V transposed -> g_vt[b,h][d][m]
            int h = (n0 - 1024) >> 7;
#pragma unroll 8
            for (int p = 0; p < 128; p++) {
                int e = p * 128 + tid; int c = e >> 7; int r = e & 127;
                g_vt[(((size_t)z * HEADS + h) * HD + c) * NSP + m0 + r] = rnd_tf32(Ds[c * 133 + r] + bias[n0 + c]);
            }
        }
    } else {               // MODE 3: bias + residual, transposed -> out
#pragma unroll 8
        for (int p = 0; p < 128; p++) {
            int e = p * 128 + tid; int c = e >> 7; int r = e & 127;
            size_t off = ((size_t)z * CH + n0 + c) * NSP + m0 + r;
            outp[off] = Ds[c * 133 + r] + bias[n0 + c] + resid[off];
        }
    }
}

// ---------------------------------------------------------------------------
// Fused flash attention (tf32 mma). CTA = 128 thr (4 warps), q-tile 64.
// Each warp owns 16 q-rows; Q fragments in registers for the whole kernel.
// Streams 16 k-tiles of 64 keys; two smem buffers (8704 floats each):
//   bufA: K-tile [64 keys][128 d] stride 132 (and output staging at end)
//   bufB: Q staging, then V-tiles [128 d][64 keys] stride 68
// Online softmax on mma accumulator layout; P remapped via quad shuffles.
// grid = (NSP/64, BATCH*HEADS)
// ---------------------------------------------------------------------------
#define FL_BUF 8704
#define FL_SMEM (2*FL_BUF*4)   // 69632 bytes

__global__ __launch_bounds__(128) void flash_kernel()
{
    extern __shared__ float sm[];
    float* bufA = sm;
    float* bufB = sm + FL_BUF;
    const int tid = threadIdx.x;
    uint32_t smb = smem_u32(sm);
    const int lane = tid & 31, wid = tid >> 5;
    const int g = lane >> 2, t = lane & 3;

    int n0 = blockIdx.x * 64;
    int bh = blockIdx.y;
    int b = bh >> 2, h = bh & 3;
    const float* qbase = g_qkvt + (size_t)b * NSP * 1536 + h * HD;
    const float* kbase = qbase + 512;
    const float* vbase = g_vt + (size_t)bh * HD * NSP;

    // Stage Q -> bufB, K_0 -> bufA. Each tile = 64 rows x 128 floats =
    // 2048 float4 chunks; 16 chunks per thread.
    {
        uint32_t qs = smb + FL_BUF * 4;
        uint32_t ks = smb;
#pragma unroll
        for (int tr = 0; tr < 16; tr++) {
            int id = tr * 128 + tid; int r = id >> 5, f = id & 31;
            cp16(qs + (uint32_t)(r * 132 + f * 4) * 4u, qbase + (size_t)(n0 + r) * 1536 + f * 4);
        }
        CP_COMMIT();
#pragma unroll
        for (int tr = 0; tr < 16; tr++) {
            int id = tr * 128 + tid; int r = id >> 5, f = id & 31;
            cp16(ks + (uint32_t)(r * 132 + f * 4) * 4u, kbase + (size_t)r * 1536 + f * 4);
        }
        CP_COMMIT();
    }
    CP_WAIT1();          // Q resident (K_0 still in flight)
    __syncthreads();

    // Q fragments (m16 x 16 k8), persistent in registers
    uint32_t qf[16][4];
    {
        const float* Qs = bufB;
        int r = wid * 16 + g;
#pragma unroll
        for (int ks = 0; ks < 16; ks++) {
            qf[ks][0] = __float_as_uint(Qs[r * 132 + ks * 8 + t]);
            qf[ks][1] = __float_as_uint(Qs[(r + 8) * 132 + ks * 8 + t]);
            qf[ks][2] = __float_as_uint(Qs[r * 132 + ks * 8 + t + 4]);
            qf[ks][3] = __float_as_uint(Qs[(r + 8) * 132 + ks * 8 + t + 4]);
        }
    }
    __syncthreads();     // all warps done with Q before V_0 overwrites bufB

    float oacc[16][4];
#pragma unroll
    for (int i = 0; i < 16; i++)
#pragma unroll
        for (int q = 0; q < 4; q++) oacc[i][q] = 0.f;
    float rowm[2] = {-1e30f, -1e30f};
    float rowl[2] = {0.f, 0.f};

    for (int it = 0; it < 16; it++) {
        CP_WAIT0();      // K_it resident
        __syncthreads();

        // prefetch V_it -> bufB ([128 d][64 keys], stride 68):
        // 128 x 64 floats = 2048 float4 chunks; 16 per thread.
        {
            uint32_t vs = smb + FL_BUF * 4;
#pragma unroll
            for (int tr = 0; tr < 16; tr++) {
                int id = tr * 128 + tid; int d = id >> 4, f = id & 15;
                cp16(vs + (uint32_t)(d * 68 + f * 4) * 4u,
                     vbase + (size_t)d * NSP + it * 64 + f * 4);
            }
            CP_COMMIT();
        }

        // S = Q K^T (warp: 16 q x 64 keys = 8 n8, K-accum over 16 k8)
        float sacc[8][4];
#pragma unroll
        for (int i = 0; i < 8; i++)
#pragma unroll
            for (int q = 0; q < 4; q++) sacc[i][q] = 0.f;

        const float* Ks = bufA;
#pragma unroll
        for (int nt = 0; nt < 8; nt++) {
            int n = nt * 8 + g;
#pragma unroll
            for (int ks = 0; ks < 16; ks++) {
                uint32_t bb[2];
                bb[0] = __float_as_uint(Ks[n * 132 + ks * 8 + t]);
                bb[1] = __float_as_uint(Ks[n * 132 + ks * 8 + t + 4]);
                MMA8(sacc[nt], qf[ks], bb);
            }
        }

        // online softmax (rows: g -> idx 0, g+8 -> idx 1)
        float tm0 = -1e30f, tm1 = -1e30f;
#pragma unroll
        for (int nt = 0; nt < 8; nt++) {
            sacc[nt][0] *= ATT_SCALE; sacc[nt][1] *= ATT_SCALE;
            sacc[nt][2] *= ATT_SCALE; sacc[nt][3] *= ATT_SCALE;
            tm0 = fmaxf(tm0, fmaxf(sacc[nt][0], sacc[nt][1]));
            tm1 = fmaxf(tm1, fmaxf(sacc[nt][2], sacc[nt][3]));
        }
#pragma unroll
        for (int o = 1; o < 4; o <<= 1) {
            tm0 = fmaxf(tm0, __shfl_xor_sync(0xffffffffu, tm0, o));
            tm1 = fmaxf(tm1, __shfl_xor_sync(0xffffffffu, tm1, o));
        }
        float mn0 = fmaxf(rowm[0], tm0), mn1 = fmaxf(rowm[1], tm1);
        float al0 = __expf(rowm[0] - mn0), al1 = __expf(rowm[1] - mn1);
        float ts0 = 0.f, ts1 = 0.f;
#pragma unroll
        for (int nt = 0; nt < 8; nt++) {
            sacc[nt][0] = __expf(sacc[nt][0] - mn0);
            sacc[nt][1] = __expf(sacc[nt][1] - mn0);
            sacc[nt][2] = __expf(sacc[nt][2] - mn1);
            sacc[nt][3] = __expf(sacc[nt][3] - mn1);
            ts0 += sacc[nt][0] + sacc[nt][1];
            ts1 += sacc[nt][2] + sacc[nt][3];
        }
#pragma unroll
        for (int o = 1; o < 4; o <<= 1) {
            ts0 += __shfl_xor_sync(0xffffffffu, ts0, o);
            ts1 += __shfl_xor_sync(0xffffffffu, ts1, o);
        }
        rowl[0] = rowl[0] * al0 + ts0;
        rowl[1] = rowl[1] * al1 + ts1;
        rowm[0] = mn0; rowm[1] = mn1;
#pragma unroll
        for (int nt = 0; nt < 16; nt++) {
            oacc[nt][0] *= al0; oacc[nt][1] *= al0;
            oacc[nt][2] *= al1; oacc[nt][3] *= al1;
        }

        CP_WAIT0();      // V_it resident
        __syncthreads(); // also: all warps done reading K_it from bufA

        if (it < 15) {   // prefetch K_{it+1} -> bufA
            uint32_t ks = smb;
            const float* kb = kbase + (size_t)(it + 1) * 64 * 1536;
#pragma unroll
            for (int tr = 0; tr < 16; tr++) {
                int id = tr * 128 + tid; int r = id >> 5, f = id & 31;
                cp16(ks + (uint32_t)(r * 132 + f * 4) * 4u, kb + (size_t)r * 1536 + f * 4);
            }
            CP_COMMIT();
        }

        // O += P V^T  (P remapped from C-layout to A-fragment layout)
        const float* Vs = bufB;
        const int srcA = (lane & ~3) | (t >> 1);
        const int srcB = srcA + 2;
#pragma unroll
        for (int kt = 0; kt < 8; kt++) {
            float v0 = __shfl_sync(0xffffffffu, sacc[kt][0], srcA);
            float v1 = __shfl_sync(0xffffffffu, sacc[kt][1], srcA);
            float w0 = __shfl_sync(0xffffffffu, sacc[kt][0], srcB);
            float w1 = __shfl_sync(0xffffffffu, sacc[kt][1], srcB);
            float x0 = __shfl_sync(0xffffffffu, sacc[kt][2], srcA);
            float x1 = __shfl_sync(0xffffffffu, sacc[kt][3], srcA);
            float y0 = __shfl_sync(0xffffffffu, sacc[kt][2], srcB);
            float y1 = __shfl_sync(0xffffffffu, sacc[kt][3], srcB);
            uint32_t pa[4];
            pa[0] = cvt_tf32((t & 1) ? v1 : v0);
            pa[1] = cvt_tf32((t & 1) ? x1 : x0);
            pa[2] = cvt_tf32((t & 1) ? w1 : w0);
            pa[3] = cvt_tf32((t & 1) ? y1 : y0);
#pragma unroll
            for (int nt = 0; nt < 16; nt++) {
                int n = nt * 8 + g;
                uint32_t bb[2];
                bb[0] = __float_as_uint(Vs[n * 68 + kt * 8 + t]);
                bb[1] = __float_as_uint(Vs[n * 68 + kt * 8 + t + 4]);
                MMA8(oacc[nt], pa, bb);
            }
        }
    }

    // normalize, stage through bufA, write g_ot[b][q][h*128+d] (tf32-rounded)
    float inv0 = 1.f / rowl[0], inv1 = 1.f / rowl[1];
    __syncthreads();
    float* Os = bufA;
    {
        int r = wid * 16 + g;
#pragma unroll
        for (int nt = 0; nt < 16; nt++) {
            int d = nt * 8 + 2 * t;
            Os[r * 132 + d]           = oacc[nt][0] * inv0;
            Os[r * 132 + d + 1]       = oacc[nt][1] * inv0;
            Os[(r + 8) * 132 + d]     = oacc[nt][2] * inv1;
            Os[(r + 8) * 132 + d + 1] = oacc[nt][3] * inv1;
        }
    }
    __syncthreads();
    // 64 rows x 128 floats = 2048 float4 chunks; 16 per thread.
#pragma unroll
    for (int tr = 0; tr < 16; tr++) {
        int id = tr * 128 + tid;
        int row = id >> 5, f = id & 31;
        float4 v = *(float4*)&Os[row * 132 + f * 4];
        v.x = rnd_tf32(v.x); v.y = rnd_tf32(v.y);
        v.z = rnd_tf32(v.z); v.w = rnd_tf32(v.w);
        *(float4*)&g_ot[((size_t)b * NSP + n0 + row) * CH + h * HD + f * 4] = v;
    }
}

// ---------------------------------------------------------------------------
// Launch
// ---------------------------------------------------------------------------
extern "C" void kernel_launch(void* const* d_in, const int* in_sizes, int n_in,
                              void* d_out, int out_size)
{
    const float* x      = (const float*)d_in[0];
    const float* norm_w = (const float*)d_in[1];
    const float* norm_b = (const float*)d_in[2];
    const float* qkv_w  = (const float*)d_in[3];
    const float* qkv_b  = (const float*)d_in[4];
    const float* proj_w = (const float*)d_in[5];
    const float* proj_b = (const float*)d_in[6];
    float* out = (float*)d_out;

    float* wq; cudaGetSymbolAddress((void**)&wq, g_wq);
    float* wp; cudaGetSymbolAddress((void**)&wp, g_wp);

    cudaFuncSetAttribute(gemm_tc<0>, cudaFuncAttributeMaxDynamicSharedMemorySize, GEMM_SMEM);
    cudaFuncSetAttribute(gemm_tc<3>, cudaFuncAttributeMaxDynamicSharedMemorySize, GEMM_SMEM);
    cudaFuncSetAttribute(flash_kernel, cudaFuncAttributeMaxDynamicSharedMemorySize, FL_SMEM);

    cvtw_kernel<<<(3 * CH * CH + 255) / 256, 256>>>(qkv_w, proj_w);
    gn_kernel<<<BATCH * GROUPS_N, 256>>>(x, norm_w, norm_b);

    gemm_tc<0><<<dim3(NSP / 128, 1536 / 128, BATCH), 128, GEMM_SMEM>>>(wq, nullptr, qkv_b, nullptr, nullptr);
    flash_kernel<<<dim3(NSP / 64, BATCH * HEADS), 128, FL_SMEM>>>();
    gemm_tc<3><<<dim3(NSP / 128, CH / 128, BATCH), 128, GEMM_SMEM>>>(nullptr, wp, proj_b, x, out);
}